// round 13
// baseline (speedup 1.0000x reference)
#include <cuda_runtime.h>
#include <math_constants.h>

#define HH 256
#define WW 256
#define NIMG 512          // B*C = 8*64
#define CCH 64
#define HWSZ 65536        // 256*256
#define NSEG 14           // segments per image (4x19 + 10x18 rows)
#define NCHUNK (NIMG * HH * 16)

// Scratch (static device globals — no runtime allocation)
__device__ float g_cmax32[NIMG * HH * 32];    // per-(row, lane=8col) max of dst
__device__ float g_segmax[NIMG * NSEG];       // per-segment max of dst
__device__ float g_tmax[NIMG];                // 0.7 * per-image max
__device__ int   g_list[NCHUNK];              // flagged chunk ids
__device__ int   g_count;

__device__ __forceinline__ int rrow(int r) {
    return r < 0 ? -r : (r >= HH ? 2*HH - 2 - r : r);
}

// clamp dynamic local-array index into [0,4] — prevents speculative
// out-of-frame LDL when ptxas flattens the border branches into selects
#define CL(i) (min(max((int)(i), 0), 4))

// ---------------------------------------------------------------------------
// Pass A: Harris response R -> per-lane chunk maxes of the 3x3-dilated field
// (dst itself never materialized), segment maxes, out=x copy fused into the
// xc stencil loads. One warp per (image, segment); lane owns 8 cols.
// x-window state is ONE row (xb); row p-1 is reloaded on demand (L1-hit) —
// frees 8 persistent regs so 18 blocks/SM fit (113-reg cap).
// All FP contractions pinned with explicit fmaf so the apply path can
// recompute dst bit-identically.
// ---------------------------------------------------------------------------

// Load x row r (reflect-101), no out store (prev-row reloads).
#define LOAD_XROW_NS(r, dst_)  do {                                           \
    int rr__ = (r);                                                           \
    rr__ = (rr__ < 0) ? -rr__ : ((rr__ >= HH) ? (2*HH - 2 - rr__) : rr__);    \
    const float4* p__ = reinterpret_cast<const float4*>(xim + rr__ * WW + cb);\
    float4 q0__ = p__[0], q1__ = p__[1];                                      \
    dst_[0]=q0__.x; dst_[1]=q0__.y; dst_[2]=q0__.z; dst_[3]=q0__.w;           \
    dst_[4]=q1__.x; dst_[5]=q1__.y; dst_[6]=q1__.z; dst_[7]=q1__.w;           \
} while(0)

// Load x row r (reflect-101); if the REQUESTED row is in this segment, also
// store it to out (each segment row passes through the xc path exactly once).
#define LOAD_XROW_ST(r, dst_)  do {                                           \
    int rq__ = (r);                                                           \
    int rr__ = (rq__ < 0) ? -rq__ : ((rq__ >= HH) ? (2*HH - 2 - rq__) : rq__);\
    const float4* p__ = reinterpret_cast<const float4*>(xim + rr__ * WW + cb);\
    float4 q0__ = p__[0], q1__ = p__[1];                                      \
    dst_[0]=q0__.x; dst_[1]=q0__.y; dst_[2]=q0__.z; dst_[3]=q0__.w;           \
    dst_[4]=q1__.x; dst_[5]=q1__.y; dst_[6]=q1__.z; dst_[7]=q1__.w;           \
    if ((unsigned)(rq__ - r0) < (unsigned)seglen) {                           \
        float4* po__ = reinterpret_cast<float4*>(oim + rq__ * WW + cb);       \
        po__[0] = q0__; po__[1] = q1__;                                       \
    }                                                                         \
} while(0)

#define COMPUTE_DD(row, AX, AXY, AY) do {                                     \
    float xp__[8]; LOAD_XROW_NS((row)-1, xp__);   /* L1-hit reload */         \
    float xc__[8]; LOAD_XROW_ST((row)+1, xc__);                               \
    float u__[8], v__[8];                                                     \
    _Pragma("unroll")                                                         \
    for (int i=0;i<8;i++){ u__[i] = fmaf(2.0f, xb[i], xp__[i]) + xc__[i];     \
                           v__[i] = xc__[i] - xp__[i]; }                      \
    float uL__ = __shfl_up_sync(0xffffffffu, u__[7], 1);                      \
    float uR__ = __shfl_down_sync(0xffffffffu, u__[0], 1);                    \
    float vL__ = __shfl_up_sync(0xffffffffu, v__[7], 1);                      \
    float vR__ = __shfl_down_sync(0xffffffffu, v__[0], 1);                    \
    if (lane == 0)  { uL__ = u__[1]; vL__ = v__[1]; }                         \
    if (lane == 31) { uR__ = u__[6]; vR__ = v__[6]; }                         \
    _Pragma("unroll")                                                         \
    for (int i=0;i<8;i++){                                                    \
        float um1__ = (i==0)? uL__ : u__[i-1];                                \
        float up1__ = (i==7)? uR__ : u__[i+1];                                \
        float vm1__ = (i==0)? vL__ : v__[i-1];                                \
        float vp1__ = (i==7)? vR__ : v__[i+1];                                \
        float dx__ = (up1__ - um1__) * SC;                                    \
        float dy__ = (fmaf(2.0f, v__[i], vm1__) + vp1__) * SC;                \
        AX[i] = dx__*dx__; AXY[i] = dx__*dy__; AY[i] = dy__*dy__;             \
    }                                                                         \
    _Pragma("unroll")                                                         \
    for (int i=0;i<8;i++){ xb[i] = xc__[i]; }                                 \
} while(0)

// Horizontal sums + R + per-lane row max h + emit chunkmax row q = PV-1.
#define EMIT_P(PV) do {                                                       \
    float xxL__ = __shfl_up_sync(0xffffffffu, sxx[7],1);                      \
    float xxR__ = __shfl_down_sync(0xffffffffu, sxx[0],1);                    \
    float xyL__ = __shfl_up_sync(0xffffffffu, sxy[7],1);                      \
    float xyR__ = __shfl_down_sync(0xffffffffu, sxy[0],1);                    \
    float yyL__ = __shfl_up_sync(0xffffffffu, syy[7],1);                      \
    float yyR__ = __shfl_down_sync(0xffffffffu, syy[0],1);                    \
    if (lane==0){  xxL__=sxx[1]; xyL__=sxy[1]; yyL__=syy[1]; }                \
    if (lane==31){ xxR__=sxx[6]; xyR__=sxy[6]; yyR__=syy[6]; }                \
    float Rv__[8];                                                            \
    _Pragma("unroll")                                                         \
    for (int i=0;i<8;i++){                                                    \
        float ixx = (((i==0)?xxL__:sxx[i-1]) + sxx[i]) + ((i==7)?xxR__:sxx[i+1]);\
        float ixy = (((i==0)?xyL__:sxy[i-1]) + sxy[i]) + ((i==7)?xyR__:sxy[i+1]);\
        float iyy = (((i==0)?yyL__:syy[i-1]) + syy[i]) + ((i==7)?yyR__:syy[i+1]);\
        float t1__ = ixy * ixy;                                               \
        float det__ = fmaf(ixx, iyy, -t1__);                                  \
        float tr__  = ixx + iyy;                                              \
        float t2__ = tr__ * tr__;                                             \
        Rv__[i] = fmaf(-0.04f, t2__, det__);                                  \
    }                                                                         \
    float RL__ = __shfl_up_sync(0xffffffffu, Rv__[7],1);                      \
    float RR__ = __shfl_down_sync(0xffffffffu, Rv__[0],1);                    \
    if (lane==0)  RL__ = -CUDART_INF_F;                                       \
    if (lane==31) RR__ = -CUDART_INF_F;                                       \
    float hc__ = fmaxf(RL__, RR__);                                           \
    _Pragma("unroll")                                                         \
    for (int i=0;i<8;i++) hc__ = fmaxf(hc__, Rv__[i]);                        \
    int q__ = (PV) - 1;                                                       \
    if (q__ >= r0) {                                                          \
        float cm__ = fmaxf(fmaxf(hb, ha), hc__);                              \
        lmax = fmaxf(lmax, cm__);                                             \
        g_cmax32[((img<<8)+q__)*32 + lane] = cm__;                            \
    }                                                                         \
    hb = ha; ha = hc__;                                                       \
} while(0)

__global__ void __launch_bounds__(32, 18) harris_kernel(const float* __restrict__ x,
                                                        float* __restrict__ out) {
    if (blockIdx.x == 0 && threadIdx.x == 0) g_count = 0;   // reset list
    const int img  = blockIdx.x / NSEG;
    const int seg  = blockIdx.x - img * NSEG;
    const int lane = threadIdx.x;
    const int cb   = lane * 8;
    const float* __restrict__ xim = x + (size_t)img * HWSZ;
    float* __restrict__ oim = out + (size_t)img * HWSZ;

    // 4 segments of 19 rows then 10 of 18 rows (total 256)
    const int r0     = seg * 18 + min(seg, 4);
    const int seglen = 18 + (seg < 4 ? 1 : 0);
    const int r1     = r0 + seglen;

    const float SC = (1.0f / 12.0f);   // SOBEL_SCALE
    float xb[8];                       // single persistent x row
    float p2x[8], p2y[8], p2z[8];      // P2 = dd(p-1)+dd(p)   (xx,xy,yy)
    float cx[8],  cy[8],  cz[8];       // C  = dd(p)
    float ha = -CUDART_INF_F, hb = -CUDART_INF_F;  // h(p-1), h(p-2)
    float lmax = -CUDART_INF_F;

    int pstart;
    if (r0 == 0) {
        LOAD_XROW_ST(0, xb);           // row 0 stored here (only time)
        COMPUTE_DD(0, cx, cy, cz);     // prev = reflect(-1)=1 NS, xc = 1 ST
#pragma unroll
        for (int i=0;i<8;i++){ p2x[i]=cx[i]+cx[i]; p2y[i]=cy[i]+cy[i]; p2z[i]=cz[i]+cz[i]; }
        // peeled p == 0 iteration (emits q=-1: nothing; shifts ha/hb)
        {
            float nx[8], ny[8], nz[8];
            COMPUTE_DD(1, nx, ny, nz);
            float sxx[8], sxy[8], syy[8];
#pragma unroll
            for (int i=0;i<8;i++){ sxx[i]=fmaf(2.0f, nx[i], cx[i]);
                                   sxy[i]=fmaf(2.0f, ny[i], cy[i]);
                                   syy[i]=fmaf(2.0f, nz[i], cz[i]); }
#pragma unroll
            for (int i=0;i<8;i++){ p2x[i]=cx[i]+nx[i]; cx[i]=nx[i];
                                   p2y[i]=cy[i]+ny[i]; cy[i]=ny[i];
                                   p2z[i]=cz[i]+nz[i]; cz[i]=nz[i]; }
            EMIT_P(0);
        }
        pstart = 1;
    } else {
        float d1x[8], d1y[8], d1z[8];
        LOAD_XROW_NS(r0 - 2, xb);
        COMPUTE_DD(r0 - 2, d1x, d1y, d1z);   // xc = r0-1 (predicate false)
        COMPUTE_DD(r0 - 1, cx, cy, cz);      // xc = r0 -> stores row r0
#pragma unroll
        for (int i=0;i<8;i++){ p2x[i]=d1x[i]+cx[i]; p2y[i]=d1y[i]+cy[i]; p2z[i]=d1z[i]+cz[i]; }
        pstart = r0 - 1;
    }

    const int pend = (r1 == HH) ? (HH - 1) : (r1 + 1);
#pragma unroll 2
    for (int p = pstart; p < pend; ++p) {
        float nx[8], ny[8], nz[8];
        COMPUTE_DD(p+1, nx, ny, nz);
        float sxx[8], sxy[8], syy[8];
#pragma unroll
        for (int i=0;i<8;i++){ sxx[i]=p2x[i]+nx[i];
                               sxy[i]=p2y[i]+ny[i];
                               syy[i]=p2z[i]+nz[i]; }
#pragma unroll
        for (int i=0;i<8;i++){ p2x[i]=cx[i]+nx[i]; cx[i]=nx[i];
                               p2y[i]=cy[i]+ny[i]; cy[i]=ny[i];
                               p2z[i]=cz[i]+nz[i]; cz[i]=nz[i]; }
        EMIT_P(p);
    }

    if (r1 == HH) {
        // peel p = 255: vertical sum = dd(255) + 2*(p2-dd(255)) (= +2*dd(254))
        float sxx[8], sxy[8], syy[8];
#pragma unroll
        for (int i=0;i<8;i++){
            sxx[i] = fmaf(2.0f, p2x[i] - cx[i], cx[i]);
            sxy[i] = fmaf(2.0f, p2y[i] - cy[i], cy[i]);
            syy[i] = fmaf(2.0f, p2z[i] - cz[i], cz[i]);
        }
        EMIT_P(255);
        // bottom image row: chunkmax(255) = max(h(254), h(255))
        float cm = fmaxf(hb, ha);
        lmax = fmaxf(lmax, cm);
        g_cmax32[((img<<8)+(HH-1))*32 + lane] = cm;
    }

#pragma unroll
    for (int o=16;o;o>>=1) lmax = fmaxf(lmax, __shfl_xor_sync(0xffffffffu, lmax, o));
    if (lane == 0) g_segmax[img * NSEG + seg] = lmax;
}

// ---------------------------------------------------------------------------
// Scan: compute t per image, compact flagged chunks (cmax >= t) into g_list
// with warp-aggregated atomics. Each thread covers 2 chunks via one float4.
// Grid: 4096 blocks x 256 (8 blocks per image).
// ---------------------------------------------------------------------------
__global__ void scan_kernel() {
    __shared__ float s14[NSEG];
    const int img = blockIdx.x >> 3;
    if (threadIdx.x < NSEG) s14[threadIdx.x] = g_segmax[img * NSEG + threadIdx.x];
    // cmax load in flight before the sync
    const int pair = blockIdx.x * 256 + threadIdx.x;      // 2 chunks per thread
    const float4 v = *reinterpret_cast<const float4*>(g_cmax32 + (size_t)pair * 4);
    __syncthreads();
    float m = s14[0];
#pragma unroll
    for (int i = 1; i < NSEG; i++) m = fmaxf(m, s14[i]);
    const float t = 0.7f * m;   // THRESH_FRAC
    if ((blockIdx.x & 7) == 0 && threadIdx.x == 0) g_tmax[img] = t;

    int cid0 = pair * 2;
    bool f0 = fmaxf(v.x, v.y) >= t;
    bool f1 = fmaxf(v.z, v.w) >= t;

    unsigned b0 = __ballot_sync(0xffffffffu, f0);
    unsigned b1 = __ballot_sync(0xffffffffu, f1);
    int n0 = __popc(b0);
    int tot = n0 + __popc(b1);
    if (tot) {
        int lane = threadIdx.x & 31;
        unsigned lt = (1u << lane) - 1u;
        int basep = 0;
        if (lane == 0) basep = atomicAdd(&g_count, tot);
        basep = __shfl_sync(0xffffffffu, basep, 0);
        if (f0) g_list[basep + __popc(b0 & lt)] = cid0;
        if (f1) g_list[basep + n0 + __popc(b1 & lt)] = cid0 + 1;
    }
}

// ---------------------------------------------------------------------------
// Apply: 16K warps grid-stride the compacted list — one chunk per warp,
// declustered across the whole chip. Per chunk: 21 upfront parallel x loads,
// recompute dst bit-identical to pass A, then PIXEL-PER-LANE conv: lanes
// 0-15 own the chunk's 16 pixels (channels 0-31), lanes 16-31 same pixels
// (channels 32-63); 32 independent strided loads (one latency window), one
// shfl merge, predicated store.
// ---------------------------------------------------------------------------
__global__ void apply_kernel(const float* __restrict__ x, const float* __restrict__ wt,
                             const float* __restrict__ bias, float* __restrict__ out) {
    const int gwarp  = (blockIdx.x * blockDim.x + threadIdx.x) >> 5;
    const int nwarps = (gridDim.x * blockDim.x) >> 5;
    const int lane = threadIdx.x & 31;
    const float SC = (1.0f / 12.0f);
    const int total = g_count;
    const int half = lane >> 4;          // channel half (0: ci 0-31, 1: ci 32-63)
    const int px   = lane & 15;          // pixel index within chunk

    for (int li = gwarp; li < total; li += nwarps) {
        int cid = g_list[li];
        int img = cid >> 12;
        int rc  = cid & 4095;
        int q   = rc >> 4;
        int c0  = (rc & 15) << 4;
        float t = g_tmax[img];
        const float* __restrict__ xim = x + (size_t)img * HWSZ;

        int c  = c0 - 2 + lane;                 // field column
        int cc = (c < 0) ? -c : (c >= WW ? 2*WW - 2 - c : c);
        int cL = (cc == 0) ? 1 : cc - 1;        // reflect-101 col for x loads
        int cR = (cc == WW-1) ? WW-2 : cc + 1;

        int dlo = q - 2 < 0 ? 0 : q - 2;

        // Upfront parallel loads: 7 rows x 3 cols (independent -> MLP 21).
        float xr0[7], xr1[7], xr2[7];
#pragma unroll
        for (int j = 0; j < 7; ++j) {
            int rj = rrow(dlo - 1 + j) * WW;
            xr0[j] = xim[rj + cL];
            xr1[j] = xim[rj + cc];
            xr2[j] = xim[rj + cR];
        }
        float xq = xim[q * WW + cc];            // x at (q, cc) for the mask

        float ddx[5], ddxy[5], ddy2[5];
#pragma unroll
        for (int k = 0; k < 5; ++k) {           // d = dlo + k (k>span unused)
            float uL = fmaf(2.0f, xr0[k+1], xr0[k]) + xr0[k+2];
            float uR = fmaf(2.0f, xr2[k+1], xr2[k]) + xr2[k+2];
            float vL = xr0[k+2] - xr0[k];
            float vC = xr1[k+2] - xr1[k];
            float vR = xr2[k+2] - xr2[k];
            float dx = (uR - uL) * SC;
            float dy = (fmaf(2.0f, vC, vL) + vR) * SC;
            ddx[k]  = dx * dx;
            ddxy[k] = dx * dy;
            ddy2[k] = dy * dy;
        }

        float dstv = -CUDART_INF_F;
        for (int rr = q - 1; rr <= q + 1; ++rr) {
            if (rr < 0 || rr > HH - 1) continue;
            float sxx, sxy, syy;
            if (rr == 0) {
                sxx = fmaf(2.0f, ddx[CL(1 - dlo)],  ddx[CL(0 - dlo)]);
                sxy = fmaf(2.0f, ddxy[CL(1 - dlo)], ddxy[CL(0 - dlo)]);
                syy = fmaf(2.0f, ddy2[CL(1 - dlo)], ddy2[CL(0 - dlo)]);
            } else if (rr == HH - 1) {
                float p2a = ddx[CL(254 - dlo)]  + ddx[CL(255 - dlo)];
                float p2b = ddxy[CL(254 - dlo)] + ddxy[CL(255 - dlo)];
                float p2c = ddy2[CL(254 - dlo)] + ddy2[CL(255 - dlo)];
                sxx = fmaf(2.0f, p2a - ddx[CL(255 - dlo)],  ddx[CL(255 - dlo)]);
                sxy = fmaf(2.0f, p2b - ddxy[CL(255 - dlo)], ddxy[CL(255 - dlo)]);
                syy = fmaf(2.0f, p2c - ddy2[CL(255 - dlo)], ddy2[CL(255 - dlo)]);
            } else {
                sxx = (ddx[CL(rr - 1 - dlo)]  + ddx[CL(rr - dlo)])  + ddx[CL(rr + 1 - dlo)];
                sxy = (ddxy[CL(rr - 1 - dlo)] + ddxy[CL(rr - dlo)]) + ddxy[CL(rr + 1 - dlo)];
                syy = (ddy2[CL(rr - 1 - dlo)] + ddy2[CL(rr - dlo)]) + ddy2[CL(rr + 1 - dlo)];
            }
            float xxm = __shfl_up_sync(0xffffffffu, sxx, 1);
            float xxp = __shfl_down_sync(0xffffffffu, sxx, 1);
            float xym = __shfl_up_sync(0xffffffffu, sxy, 1);
            float xyp = __shfl_down_sync(0xffffffffu, sxy, 1);
            float yym = __shfl_up_sync(0xffffffffu, syy, 1);
            float yyp = __shfl_down_sync(0xffffffffu, syy, 1);
            float ixx = (xxm + sxx) + xxp;
            float ixy = (xym + sxy) + xyp;
            float iyy = (yym + syy) + yyp;
            float t1 = ixy * ixy;
            float det = fmaf(ixx, iyy, -t1);
            float tr  = ixx + iyy;
            float t2 = tr * tr;
            float Rv = fmaf(-0.04f, t2, det);
            if (c < 0 || c > WW - 1) Rv = -CUDART_INF_F;   // dilation clips
            float Rm = __shfl_up_sync(0xffffffffu, Rv, 1);
            float Rp = __shfl_down_sync(0xffffffffu, Rv, 1);
            float mm = fmaxf(fmaxf(Rm, Rv), Rp);
            dstv = fmaxf(dstv, mm);
        }

        bool flg = (lane >= 2) && (lane < 18) && (dstv >= t);
        unsigned bal = __ballot_sync(0xffffffffu, flg);
        if (bal) {
            int b   = img >> 6;
            int cch = img & 63;
            float bi = bias[cch];
            const float* wr = wt + (cch << 6) + half * 32;
            const float* xp = x + ((size_t)(b << 6) + half * 32) * HWSZ
                                + ((q << 8) + c0 + px);
            float acc = 0.0f;
#pragma unroll
            for (int j = 0; j < 32; ++j)
                acc = fmaf(wr[j], xp[(size_t)j * HWSZ], acc);
            acc += __shfl_down_sync(0xffffffffu, acc, 16);   // merge channel halves
            float dpix = __shfl_sync(0xffffffffu, dstv, px + 2);
            float xpix = __shfl_sync(0xffffffffu, xq,   px + 2);
            if (half == 0 && ((bal >> (px + 2)) & 1u)) {
                float y = fmaxf(acc + bi, 0.0f);
                float mask = (dpix > t) ? 1.0f : xpix;       // tie keeps pixel
                out[(size_t)img * HWSZ + ((q << 8) + c0 + px)] = fmaf(mask, y, xpix);
            }
        }
    }
}

extern "C" void kernel_launch(void* const* d_in, const int* in_sizes, int n_in,
                              void* d_out, int out_size) {
    const float* x = (const float*)d_in[0];
    const float* w = (const float*)d_in[1];
    const float* b = (const float*)d_in[2];
    float* out = (float*)d_out;
    harris_kernel<<<NIMG * NSEG, 32>>>(x, out);
    scan_kernel<<<4096, 256>>>();
    apply_kernel<<<2048, 256>>>(x, w, b, out);
}

// round 14
// speedup vs baseline: 1.1214x; 1.1214x over previous
#include <cuda_runtime.h>
#include <math_constants.h>

#define HH 256
#define WW 256
#define NIMG 512          // B*C = 8*64
#define CCH 64
#define HWSZ 65536        // 256*256
#define NSEG 14           // segments per image (4x19 + 10x18 rows)
#define NCHUNK (NIMG * HH * 16)

// Scratch (static device globals — no runtime allocation)
__device__ float g_cmax32[NIMG * HH * 32];    // per-(row, lane=8col) max of dst
__device__ float g_segmax[NIMG * NSEG];       // per-segment max of dst
__device__ float g_tmax[NIMG];                // 0.7 * per-image max
__device__ int   g_list[NCHUNK];              // flagged chunk ids
__device__ int   g_count;

__device__ __forceinline__ int rrow(int r) {
    return r < 0 ? -r : (r >= HH ? 2*HH - 2 - r : r);
}

// clamp dynamic local-array index into [0,4] — prevents speculative
// out-of-frame LDL when ptxas flattens the border branches into selects
#define CL(i) (min(max((int)(i), 0), 4))

// ---------------------------------------------------------------------------
// Packed f32x2 helpers (sm_100+). Per-half rounding is identical to the
// scalar ops, so harris (packed) and apply (scalar) stay bit-identical:
//   ffma2(-1,a,c)           == c - a          (exact -1*a, one rounding)
//   fadd2(x,x)              == 2x exactly     -> fadd2(fadd2(x,x),a) == fmaf(2,x,a)
//   fmul2(fmul2(y,-1),y)    == -(y*y)         (RN is sign-symmetric)
// ---------------------------------------------------------------------------
typedef unsigned long long ull_t;
#define U64REF(x) (*reinterpret_cast<ull_t*>(&(x)))
__device__ __forceinline__ float2 fadd2(float2 a, float2 b) {
    float2 r;
    asm("add.rn.f32x2 %0, %1, %2;" : "=l"(U64REF(r)) : "l"(U64REF(a)), "l"(U64REF(b)));
    return r;
}
__device__ __forceinline__ float2 fmul2(float2 a, float2 b) {
    float2 r;
    asm("mul.rn.f32x2 %0, %1, %2;" : "=l"(U64REF(r)) : "l"(U64REF(a)), "l"(U64REF(b)));
    return r;
}
__device__ __forceinline__ float2 ffma2(float2 a, float2 b, float2 c) {
    float2 r;
    asm("fma.rn.f32x2 %0, %1, %2, %3;"
        : "=l"(U64REF(r)) : "l"(U64REF(a)), "l"(U64REF(b)), "l"(U64REF(c)));
    return r;
}

// ---------------------------------------------------------------------------
// Pass A: Harris response R -> per-lane chunk maxes of the 3x3-dilated field
// (dst never materialized), segment maxes, out=x copy fused into the stencil
// row loads. One warp per (image, segment); lane owns 8 cols = 4 f32x2 pairs.
// All arithmetic packed f32x2, per-half bit-identical to the scalar apply.
// ---------------------------------------------------------------------------

// Load x row r (reflect-101) into 4 packed pairs. If the REQUESTED row lies
// in this segment, also store it to out (each row passes through once).
#define LOAD_XROW(r, dst_)  do {                                              \
    int rq__ = (r);                                                           \
    int rr__ = (rq__ < 0) ? -rq__ : ((rq__ >= HH) ? (2*HH - 2 - rq__) : rq__);\
    const float4* p__ = reinterpret_cast<const float4*>(xim + rr__ * WW + cb);\
    float4 q0__ = p__[0], q1__ = p__[1];                                      \
    dst_[0] = make_float2(q0__.x, q0__.y);                                    \
    dst_[1] = make_float2(q0__.z, q0__.w);                                    \
    dst_[2] = make_float2(q1__.x, q1__.y);                                    \
    dst_[3] = make_float2(q1__.z, q1__.w);                                    \
    if ((unsigned)(rq__ - r0) < (unsigned)seglen) {                           \
        float4* po__ = reinterpret_cast<float4*>(oim + rq__ * WW + cb);       \
        po__[0] = q0__; po__[1] = q1__;                                       \
    }                                                                         \
} while(0)

#define COMPUTE_DD(row, AX, AXY, AY) do {                                     \
    float2 xc__[4]; LOAD_XROW((row)+1, xc__);                                 \
    float2 u__[4], v__[4];                                                    \
    _Pragma("unroll")                                                         \
    for (int k=0;k<4;k++){                                                    \
        float2 t__ = fadd2(xb2[k], xb2[k]);          /* exact 2*xb */         \
        u__[k] = fadd2(fadd2(t__, xa2[k]), xc__[k]); /* ==fmaf(2,xb,xa)+xc */ \
        v__[k] = ffma2(NEG1, xa2[k], xc__[k]);       /* == xc - xa */         \
    }                                                                         \
    float uL__ = __shfl_up_sync(0xffffffffu, u__[3].y, 1);                    \
    float uR__ = __shfl_down_sync(0xffffffffu, u__[0].x, 1);                  \
    float vL__ = __shfl_up_sync(0xffffffffu, v__[3].y, 1);                    \
    float vR__ = __shfl_down_sync(0xffffffffu, v__[0].x, 1);                  \
    if (lane == 0)  { uL__ = u__[0].y; vL__ = v__[0].y; }                     \
    if (lane == 31) { uR__ = u__[3].x; vR__ = v__[3].x; }                     \
    float2 um1__[4], up1__[4], vm1__[4], vp1__[4];                            \
    um1__[0] = make_float2(uL__,     u__[0].x);                               \
    um1__[1] = make_float2(u__[0].y, u__[1].x);                               \
    um1__[2] = make_float2(u__[1].y, u__[2].x);                               \
    um1__[3] = make_float2(u__[2].y, u__[3].x);                               \
    up1__[0] = um1__[1]; up1__[1] = um1__[2]; up1__[2] = um1__[3];            \
    up1__[3] = make_float2(u__[3].y, uR__);                                   \
    vm1__[0] = make_float2(vL__,     v__[0].x);                               \
    vm1__[1] = make_float2(v__[0].y, v__[1].x);                               \
    vm1__[2] = make_float2(v__[1].y, v__[2].x);                               \
    vm1__[3] = make_float2(v__[2].y, v__[3].x);                               \
    vp1__[0] = vm1__[1]; vp1__[1] = vm1__[2]; vp1__[2] = vm1__[3];            \
    vp1__[3] = make_float2(v__[3].y, vR__);                                   \
    _Pragma("unroll")                                                         \
    for (int k=0;k<4;k++){                                                    \
        float2 dx__ = fmul2(ffma2(NEG1, um1__[k], up1__[k]), SC2);            \
        float2 tv__ = fadd2(v__[k], v__[k]);                                  \
        float2 dy__ = fmul2(fadd2(fadd2(tv__, vm1__[k]), vp1__[k]), SC2);     \
        AX[k]  = fmul2(dx__, dx__);                                           \
        AXY[k] = fmul2(dx__, dy__);                                           \
        AY[k]  = fmul2(dy__, dy__);                                           \
    }                                                                         \
    _Pragma("unroll")                                                         \
    for (int k=0;k<4;k++){ xa2[k] = xb2[k]; xb2[k] = xc__[k]; }               \
} while(0)

// Horizontal sums + R + per-lane row max h + emit chunkmax row q = PV-1.
#define EMIT_P(PV) do {                                                       \
    float xxL__ = __shfl_up_sync(0xffffffffu, sxx2[3].y,1);                   \
    float xxR__ = __shfl_down_sync(0xffffffffu, sxx2[0].x,1);                 \
    float xyL__ = __shfl_up_sync(0xffffffffu, sxy2[3].y,1);                   \
    float xyR__ = __shfl_down_sync(0xffffffffu, sxy2[0].x,1);                 \
    float yyL__ = __shfl_up_sync(0xffffffffu, syy2[3].y,1);                   \
    float yyR__ = __shfl_down_sync(0xffffffffu, syy2[0].x,1);                 \
    if (lane==0){  xxL__=sxx2[0].y; xyL__=sxy2[0].y; yyL__=syy2[0].y; }       \
    if (lane==31){ xxR__=sxx2[3].x; xyR__=sxy2[3].x; yyR__=syy2[3].x; }       \
    float2 am1__[4], ap1__[4], bm1__[4], bp1__[4], cm1__[4], cp1__[4];        \
    am1__[0] = make_float2(xxL__,      sxx2[0].x);                            \
    am1__[1] = make_float2(sxx2[0].y, sxx2[1].x);                             \
    am1__[2] = make_float2(sxx2[1].y, sxx2[2].x);                             \
    am1__[3] = make_float2(sxx2[2].y, sxx2[3].x);                             \
    ap1__[0] = am1__[1]; ap1__[1] = am1__[2]; ap1__[2] = am1__[3];            \
    ap1__[3] = make_float2(sxx2[3].y, xxR__);                                 \
    bm1__[0] = make_float2(xyL__,      sxy2[0].x);                            \
    bm1__[1] = make_float2(sxy2[0].y, sxy2[1].x);                             \
    bm1__[2] = make_float2(sxy2[1].y, sxy2[2].x);                             \
    bm1__[3] = make_float2(sxy2[2].y, sxy2[3].x);                             \
    bp1__[0] = bm1__[1]; bp1__[1] = bm1__[2]; bp1__[2] = bm1__[3];            \
    bp1__[3] = make_float2(sxy2[3].y, xyR__);                                 \
    cm1__[0] = make_float2(yyL__,      syy2[0].x);                            \
    cm1__[1] = make_float2(syy2[0].y, syy2[1].x);                             \
    cm1__[2] = make_float2(syy2[1].y, syy2[2].x);                             \
    cm1__[3] = make_float2(syy2[2].y, syy2[3].x);                             \
    cp1__[0] = cm1__[1]; cp1__[1] = cm1__[2]; cp1__[2] = cm1__[3];            \
    cp1__[3] = make_float2(syy2[3].y, yyR__);                                 \
    float2 Rv__[4];                                                           \
    _Pragma("unroll")                                                         \
    for (int k=0;k<4;k++){                                                    \
        float2 ixx__ = fadd2(fadd2(am1__[k], sxx2[k]), ap1__[k]);             \
        float2 ixy__ = fadd2(fadd2(bm1__[k], sxy2[k]), bp1__[k]);             \
        float2 iyy__ = fadd2(fadd2(cm1__[k], syy2[k]), cp1__[k]);             \
        float2 t1n__ = fmul2(fmul2(ixy__, NEG1), ixy__);  /* == -(ixy*ixy) */ \
        float2 det__ = ffma2(ixx__, iyy__, t1n__);                            \
        float2 tr__  = fadd2(ixx__, iyy__);                                   \
        float2 t2__  = fmul2(tr__, tr__);                                     \
        Rv__[k] = ffma2(NK2, t2__, det__);                                    \
    }                                                                         \
    float RL__ = __shfl_up_sync(0xffffffffu, Rv__[3].y,1);                    \
    float RR__ = __shfl_down_sync(0xffffffffu, Rv__[0].x,1);                  \
    if (lane==0)  RL__ = -CUDART_INF_F;                                       \
    if (lane==31) RR__ = -CUDART_INF_F;                                       \
    float hc__ = fmaxf(RL__, RR__);                                           \
    _Pragma("unroll")                                                         \
    for (int k=0;k<4;k++) hc__ = fmaxf(hc__, fmaxf(Rv__[k].x, Rv__[k].y));    \
    int q__ = (PV) - 1;                                                       \
    if (q__ >= r0) {                                                          \
        float cm__ = fmaxf(fmaxf(hb, ha), hc__);                              \
        lmax = fmaxf(lmax, cm__);                                             \
        g_cmax32[((img<<8)+q__)*32 + lane] = cm__;                            \
    }                                                                         \
    hb = ha; ha = hc__;                                                       \
} while(0)

__global__ void __launch_bounds__(32, 16) harris_kernel(const float* __restrict__ x,
                                                        float* __restrict__ out) {
    if (blockIdx.x == 0 && threadIdx.x == 0) g_count = 0;   // reset list
    const int img  = blockIdx.x / NSEG;
    const int seg  = blockIdx.x - img * NSEG;
    const int lane = threadIdx.x;
    const int cb   = lane * 8;
    const float* __restrict__ xim = x + (size_t)img * HWSZ;
    float* __restrict__ oim = out + (size_t)img * HWSZ;

    // 4 segments of 19 rows then 10 of 18 rows (total 256); grid 7168 warps
    // = 3.03 waves at 16 resident blocks/SM (kills wave quantization).
    const int r0     = seg * 18 + min(seg, 4);
    const int seglen = 18 + (seg < 4 ? 1 : 0);
    const int r1     = r0 + seglen;

    const float SC = (1.0f / 12.0f);   // SOBEL_SCALE
    const float2 NEG1 = make_float2(-1.0f, -1.0f);
    const float2 SC2  = make_float2(SC, SC);
    const float2 NK2  = make_float2(-0.04f, -0.04f);

    float2 xa2[4], xb2[4];
    float2 p2x2[4], p2y2[4], p2z2[4];  // P2 = dd(p-1)+dd(p)   (xx,xy,yy)
    float2 cx2[4],  cy2[4],  cz2[4];   // C  = dd(p)
    float ha = -CUDART_INF_F, hb = -CUDART_INF_F;  // h(p-1), h(p-2)
    float lmax = -CUDART_INF_F;

    int pstart;
    if (r0 == 0) {
        LOAD_XROW(-1, xa2);
        LOAD_XROW(0,  xb2);
        COMPUTE_DD(0, cx2, cy2, cz2);
#pragma unroll
        for (int k=0;k<4;k++){ p2x2[k]=fadd2(cx2[k],cx2[k]);
                               p2y2[k]=fadd2(cy2[k],cy2[k]);
                               p2z2[k]=fadd2(cz2[k],cz2[k]); }
        // peeled p == 0 iteration (emits q=-1: nothing; shifts ha/hb)
        {
            float2 nx[4], ny[4], nz[4];
            COMPUTE_DD(1, nx, ny, nz);
            float2 sxx2[4], sxy2[4], syy2[4];
#pragma unroll
            for (int k=0;k<4;k++){   // == fmaf(2, n, c) per half (2n exact)
                sxx2[k]=fadd2(fadd2(nx[k],nx[k]), cx2[k]);
                sxy2[k]=fadd2(fadd2(ny[k],ny[k]), cy2[k]);
                syy2[k]=fadd2(fadd2(nz[k],nz[k]), cz2[k]);
            }
#pragma unroll
            for (int k=0;k<4;k++){ p2x2[k]=fadd2(cx2[k],nx[k]); cx2[k]=nx[k];
                                   p2y2[k]=fadd2(cy2[k],ny[k]); cy2[k]=ny[k];
                                   p2z2[k]=fadd2(cz2[k],nz[k]); cz2[k]=nz[k]; }
            EMIT_P(0);
        }
        pstart = 1;
    } else {
        float2 d1x[4], d1y[4], d1z[4];
        LOAD_XROW(r0 - 3, xa2);
        LOAD_XROW(r0 - 2, xb2);
        COMPUTE_DD(r0 - 2, d1x, d1y, d1z);
        COMPUTE_DD(r0 - 1, cx2, cy2, cz2);
#pragma unroll
        for (int k=0;k<4;k++){ p2x2[k]=fadd2(d1x[k],cx2[k]);
                               p2y2[k]=fadd2(d1y[k],cy2[k]);
                               p2z2[k]=fadd2(d1z[k],cz2[k]); }
        pstart = r0 - 1;
    }

    const int pend = (r1 == HH) ? (HH - 1) : (r1 + 1);
#pragma unroll 2
    for (int p = pstart; p < pend; ++p) {
        float2 nx[4], ny[4], nz[4];
        COMPUTE_DD(p+1, nx, ny, nz);
        float2 sxx2[4], sxy2[4], syy2[4];
#pragma unroll
        for (int k=0;k<4;k++){ sxx2[k]=fadd2(p2x2[k],nx[k]);
                               sxy2[k]=fadd2(p2y2[k],ny[k]);
                               syy2[k]=fadd2(p2z2[k],nz[k]); }
#pragma unroll
        for (int k=0;k<4;k++){ p2x2[k]=fadd2(cx2[k],nx[k]); cx2[k]=nx[k];
                               p2y2[k]=fadd2(cy2[k],ny[k]); cy2[k]=ny[k];
                               p2z2[k]=fadd2(cz2[k],nz[k]); cz2[k]=nz[k]; }
        EMIT_P(p);
    }

    if (r1 == HH) {
        // peel p = 255: per half == fmaf(2, p2-c, c) with p2-c via ffma2(-1,..)
        float2 sxx2[4], sxy2[4], syy2[4];
#pragma unroll
        for (int k=0;k<4;k++){
            float2 dx_ = ffma2(NEG1, cx2[k], p2x2[k]);
            float2 dy_ = ffma2(NEG1, cy2[k], p2y2[k]);
            float2 dz_ = ffma2(NEG1, cz2[k], p2z2[k]);
            sxx2[k] = fadd2(fadd2(dx_,dx_), cx2[k]);
            sxy2[k] = fadd2(fadd2(dy_,dy_), cy2[k]);
            syy2[k] = fadd2(fadd2(dz_,dz_), cz2[k]);
        }
        EMIT_P(255);
        // bottom image row: chunkmax(255) = max(h(254), h(255))
        float cm = fmaxf(hb, ha);
        lmax = fmaxf(lmax, cm);
        g_cmax32[((img<<8)+(HH-1))*32 + lane] = cm;
    }

#pragma unroll
    for (int o=16;o;o>>=1) lmax = fmaxf(lmax, __shfl_xor_sync(0xffffffffu, lmax, o));
    if (lane == 0) g_segmax[img * NSEG + seg] = lmax;
}

// ---------------------------------------------------------------------------
// Scan: compute t per image, compact flagged chunks (cmax >= t) into g_list
// with warp-aggregated atomics. Each thread covers 2 chunks via one float4.
// Grid: 4096 blocks x 256 (8 blocks per image).
// ---------------------------------------------------------------------------
__global__ void scan_kernel() {
    __shared__ float s14[NSEG];
    const int img = blockIdx.x >> 3;
    if (threadIdx.x < NSEG) s14[threadIdx.x] = g_segmax[img * NSEG + threadIdx.x];
    // cmax load in flight before the sync
    const int pair = blockIdx.x * 256 + threadIdx.x;      // 2 chunks per thread
    const float4 v = *reinterpret_cast<const float4*>(g_cmax32 + (size_t)pair * 4);
    __syncthreads();
    float m = s14[0];
#pragma unroll
    for (int i = 1; i < NSEG; i++) m = fmaxf(m, s14[i]);
    const float t = 0.7f * m;   // THRESH_FRAC
    if ((blockIdx.x & 7) == 0 && threadIdx.x == 0) g_tmax[img] = t;

    int cid0 = pair * 2;
    bool f0 = fmaxf(v.x, v.y) >= t;
    bool f1 = fmaxf(v.z, v.w) >= t;

    unsigned b0 = __ballot_sync(0xffffffffu, f0);
    unsigned b1 = __ballot_sync(0xffffffffu, f1);
    int n0 = __popc(b0);
    int tot = n0 + __popc(b1);
    if (tot) {
        int lane = threadIdx.x & 31;
        unsigned lt = (1u << lane) - 1u;
        int basep = 0;
        if (lane == 0) basep = atomicAdd(&g_count, tot);
        basep = __shfl_sync(0xffffffffu, basep, 0);
        if (f0) g_list[basep + __popc(b0 & lt)] = cid0;
        if (f1) g_list[basep + n0 + __popc(b1 & lt)] = cid0 + 1;
    }
}

// ---------------------------------------------------------------------------
// Apply: 16K warps grid-stride the compacted list — one chunk per warp,
// declustered across the whole chip. Per chunk: 21 upfront parallel x loads,
// recompute dst bit-identical to pass A, then PIXEL-PER-LANE conv: lanes
// 0-15 own the chunk's 16 pixels (channels 0-31), lanes 16-31 same pixels
// (channels 32-63); 32 independent strided loads (one latency window), one
// shfl merge, predicated store.
// ---------------------------------------------------------------------------
__global__ void apply_kernel(const float* __restrict__ x, const float* __restrict__ wt,
                             const float* __restrict__ bias, float* __restrict__ out) {
    const int gwarp  = (blockIdx.x * blockDim.x + threadIdx.x) >> 5;
    const int nwarps = (gridDim.x * blockDim.x) >> 5;
    const int lane = threadIdx.x & 31;
    const float SC = (1.0f / 12.0f);
    const int total = g_count;
    const int half = lane >> 4;          // channel half (0: ci 0-31, 1: ci 32-63)
    const int px   = lane & 15;          // pixel index within chunk

    for (int li = gwarp; li < total; li += nwarps) {
        int cid = g_list[li];
        int img = cid >> 12;
        int rc  = cid & 4095;
        int q   = rc >> 4;
        int c0  = (rc & 15) << 4;
        float t = g_tmax[img];
        const float* __restrict__ xim = x + (size_t)img * HWSZ;

        int c  = c0 - 2 + lane;                 // field column
        int cc = (c < 0) ? -c : (c >= WW ? 2*WW - 2 - c : c);
        int cL = (cc == 0) ? 1 : cc - 1;        // reflect-101 col for x loads
        int cR = (cc == WW-1) ? WW-2 : cc + 1;

        int dlo = q - 2 < 0 ? 0 : q - 2;

        // Upfront parallel loads: 7 rows x 3 cols (independent -> MLP 21).
        float xr0[7], xr1[7], xr2[7];
#pragma unroll
        for (int j = 0; j < 7; ++j) {
            int rj = rrow(dlo - 1 + j) * WW;
            xr0[j] = xim[rj + cL];
            xr1[j] = xim[rj + cc];
            xr2[j] = xim[rj + cR];
        }
        float xq = xim[q * WW + cc];            // x at (q, cc) for the mask

        float ddx[5], ddxy[5], ddy2[5];
#pragma unroll
        for (int k = 0; k < 5; ++k) {           // d = dlo + k (k>span unused)
            float uL = fmaf(2.0f, xr0[k+1], xr0[k]) + xr0[k+2];
            float uR = fmaf(2.0f, xr2[k+1], xr2[k]) + xr2[k+2];
            float vL = xr0[k+2] - xr0[k];
            float vC = xr1[k+2] - xr1[k];
            float vR = xr2[k+2] - xr2[k];
            float dx = (uR - uL) * SC;
            float dy = (fmaf(2.0f, vC, vL) + vR) * SC;
            ddx[k]  = dx * dx;
            ddxy[k] = dx * dy;
            ddy2[k] = dy * dy;
        }

        float dstv = -CUDART_INF_F;
        for (int rr = q - 1; rr <= q + 1; ++rr) {
            if (rr < 0 || rr > HH - 1) continue;
            float sxx, sxy, syy;
            if (rr == 0) {
                sxx = fmaf(2.0f, ddx[CL(1 - dlo)],  ddx[CL(0 - dlo)]);
                sxy = fmaf(2.0f, ddxy[CL(1 - dlo)], ddxy[CL(0 - dlo)]);
                syy = fmaf(2.0f, ddy2[CL(1 - dlo)], ddy2[CL(0 - dlo)]);
            } else if (rr == HH - 1) {
                float p2a = ddx[CL(254 - dlo)]  + ddx[CL(255 - dlo)];
                float p2b = ddxy[CL(254 - dlo)] + ddxy[CL(255 - dlo)];
                float p2c = ddy2[CL(254 - dlo)] + ddy2[CL(255 - dlo)];
                sxx = fmaf(2.0f, p2a - ddx[CL(255 - dlo)],  ddx[CL(255 - dlo)]);
                sxy = fmaf(2.0f, p2b - ddxy[CL(255 - dlo)], ddxy[CL(255 - dlo)]);
                syy = fmaf(2.0f, p2c - ddy2[CL(255 - dlo)], ddy2[CL(255 - dlo)]);
            } else {
                sxx = (ddx[CL(rr - 1 - dlo)]  + ddx[CL(rr - dlo)])  + ddx[CL(rr + 1 - dlo)];
                sxy = (ddxy[CL(rr - 1 - dlo)] + ddxy[CL(rr - dlo)]) + ddxy[CL(rr + 1 - dlo)];
                syy = (ddy2[CL(rr - 1 - dlo)] + ddy2[CL(rr - dlo)]) + ddy2[CL(rr + 1 - dlo)];
            }
            float xxm = __shfl_up_sync(0xffffffffu, sxx, 1);
            float xxp = __shfl_down_sync(0xffffffffu, sxx, 1);
            float xym = __shfl_up_sync(0xffffffffu, sxy, 1);
            float xyp = __shfl_down_sync(0xffffffffu, sxy, 1);
            float yym = __shfl_up_sync(0xffffffffu, syy, 1);
            float yyp = __shfl_down_sync(0xffffffffu, syy, 1);
            float ixx = (xxm + sxx) + xxp;
            float ixy = (xym + sxy) + xyp;
            float iyy = (yym + syy) + yyp;
            float t1 = ixy * ixy;
            float det = fmaf(ixx, iyy, -t1);
            float tr  = ixx + iyy;
            float t2 = tr * tr;
            float Rv = fmaf(-0.04f, t2, det);
            if (c < 0 || c > WW - 1) Rv = -CUDART_INF_F;   // dilation clips
            float Rm = __shfl_up_sync(0xffffffffu, Rv, 1);
            float Rp = __shfl_down_sync(0xffffffffu, Rv, 1);
            float mm = fmaxf(fmaxf(Rm, Rv), Rp);
            dstv = fmaxf(dstv, mm);
        }

        bool flg = (lane >= 2) && (lane < 18) && (dstv >= t);
        unsigned bal = __ballot_sync(0xffffffffu, flg);
        if (bal) {
            int b   = img >> 6;
            int cch = img & 63;
            float bi = bias[cch];
            const float* wr = wt + (cch << 6) + half * 32;
            const float* xp = x + ((size_t)(b << 6) + half * 32) * HWSZ
                                + ((q << 8) + c0 + px);
            float acc = 0.0f;
#pragma unroll
            for (int j = 0; j < 32; ++j)
                acc = fmaf(wr[j], xp[(size_t)j * HWSZ], acc);
            acc += __shfl_down_sync(0xffffffffu, acc, 16);   // merge channel halves
            float dpix = __shfl_sync(0xffffffffu, dstv, px + 2);
            float xpix = __shfl_sync(0xffffffffu, xq,   px + 2);
            if (half == 0 && ((bal >> (px + 2)) & 1u)) {
                float y = fmaxf(acc + bi, 0.0f);
                float mask = (dpix > t) ? 1.0f : xpix;       // tie keeps pixel
                out[(size_t)img * HWSZ + ((q << 8) + c0 + px)] = fmaf(mask, y, xpix);
            }
        }
    }
}

extern "C" void kernel_launch(void* const* d_in, const int* in_sizes, int n_in,
                              void* d_out, int out_size) {
    const float* x = (const float*)d_in[0];
    const float* w = (const float*)d_in[1];
    const float* b = (const float*)d_in[2];
    float* out = (float*)d_out;
    harris_kernel<<<NIMG * NSEG, 32>>>(x, out);
    scan_kernel<<<4096, 256>>>();
    apply_kernel<<<2048, 256>>>(x, w, b, out);
}